// round 6
// baseline (speedup 1.0000x reference)
#include <cuda_runtime.h>
#include <math.h>
#include <stdint.h>

#define BATCHN 4
#define SEQ    1024
#define DMODEL 1024
#define NHEAD  16
#define DHEAD  64
#define FFDIM  4096
#define NLAYER 4
#define MAXKLEN 1664
#define ROFF   640          // MAXKLEN - SEQ

// ---------------- scratch (device globals: allocation-free) ----------------
__device__ float g_X [BATCHN*SEQ*DMODEL];
__device__ float g_Q [BATCHN*SEQ*DMODEL];
__device__ float g_K [BATCHN*SEQ*DMODEL];
__device__ float g_V [BATCHN*SEQ*DMODEL];
__device__ float g_RQ[BATCHN*SEQ*DMODEL];
__device__ float g_T [BATCHN*SEQ*DMODEL];
__device__ float g_SC[(size_t)BATCHN*NHEAD*SEQ*SEQ];   // scores -> attn (in place)
__device__ float g_P [(size_t)BATCHN*NHEAD*SEQ*SEQ];   // q @ re^T + rb
__device__ float g_H [BATCHN*SEQ*FFDIM];               // FF hidden

// ---------------- helpers ----------------
__device__ __forceinline__ float gelu_exact(float x) {
    return 0.5f * x * (1.0f + erff(x * 0.70710678118654752f));
}

__device__ __forceinline__ float block_sum(float x, float* sm) {
    #pragma unroll
    for (int o = 16; o > 0; o >>= 1) x += __shfl_xor_sync(0xffffffffu, x, o);
    if ((threadIdx.x & 31) == 0) sm[threadIdx.x >> 5] = x;
    __syncthreads();
    float t = 0.f;
    #pragma unroll
    for (int w = 0; w < 8; w++) t += sm[w];
    __syncthreads();
    return t;
}

__device__ __forceinline__ float block_max(float x, float* sm) {
    #pragma unroll
    for (int o = 16; o > 0; o >>= 1) x = fmaxf(x, __shfl_xor_sync(0xffffffffu, x, o));
    if ((threadIdx.x & 31) == 0) sm[threadIdx.x >> 5] = x;
    __syncthreads();
    float t = sm[0];
    #pragma unroll
    for (int w = 1; w < 8; w++) t = fmaxf(t, sm[w]);
    __syncthreads();
    return t;
}

// ---------------- embed gather ----------------
__global__ void __launch_bounds__(256) k_embed(const int* __restrict__ seq,
                                               const float* __restrict__ emb,
                                               float* __restrict__ X) {
    int row = blockIdx.x;                 // b*SEQ + s
    int tok = seq[row];
    const float4* src = (const float4*)(emb + (size_t)tok * DMODEL);
    float4* dst = (float4*)(X + (size_t)row * DMODEL);
    dst[threadIdx.x] = src[threadIdx.x];  // 256 * 4 = 1024
}

// ---------------- q + r_w_bias ----------------
__global__ void __launch_bounds__(256) k_addrwb(const float* __restrict__ Q,
                                                const float* __restrict__ rwb,
                                                float* __restrict__ RQ) {
    size_t i = (size_t)blockIdx.x * blockDim.x + threadIdx.x;
    RQ[i] = Q[i] + rwb[i & (DMODEL - 1)];
}

// ---------------- generic TN SGEMM: C[M,N] = A[M,K] @ B[N,K]^T ----------------
// 128x128 tile, BK=8, 256 threads, 8x8 per thread. Batched over z=(b,h)
// with separate b/h pointer strides. Optional per-N bias + GELU epilogue.
__global__ void __launch_bounds__(256) k_gemm_tn(
    int M, int N, int K,
    const float* __restrict__ A, int lda, long long sAb, long long sAh,
    const float* __restrict__ B, int ldb, long long sBb, long long sBh,
    float* __restrict__ C, int ldc, long long sCb, long long sCh,
    const float* __restrict__ bias, long long sbias_h,
    int Hdiv, int act)
{
    int z  = blockIdx.z;
    int bb = z / Hdiv, hh = z % Hdiv;
    A += (long long)bb * sAb + (long long)hh * sAh;
    B += (long long)bb * sBb + (long long)hh * sBh;
    C += (long long)bb * sCb + (long long)hh * sCh;
    if (bias) bias += (long long)hh * sbias_h;

    __shared__ float As[8][128];
    __shared__ float Bs[8][128];

    int tid = threadIdx.x;
    int m0 = blockIdx.y * 128;
    int n0 = blockIdx.x * 128;
    int lr = tid >> 1;            // 0..127
    int lc = (tid & 1) << 2;      // 0 or 4
    int tx = tid & 15, ty = tid >> 4;

    const float* Ap = A + (long long)(m0 + lr) * lda + lc;
    const float* Bp = B + (long long)(n0 + lr) * ldb + lc;

    float acc[8][8];
    #pragma unroll
    for (int i = 0; i < 8; i++)
        #pragma unroll
        for (int j = 0; j < 8; j++) acc[i][j] = 0.f;

    for (int k0 = 0; k0 < K; k0 += 8) {
        float4 av = *(const float4*)(Ap + k0);
        float4 bv = *(const float4*)(Bp + k0);
        __syncthreads();
        As[lc + 0][lr] = av.x; As[lc + 1][lr] = av.y;
        As[lc + 2][lr] = av.z; As[lc + 3][lr] = av.w;
        Bs[lc + 0][lr] = bv.x; Bs[lc + 1][lr] = bv.y;
        Bs[lc + 2][lr] = bv.z; Bs[lc + 3][lr] = bv.w;
        __syncthreads();
        #pragma unroll
        for (int kk = 0; kk < 8; kk++) {
            float a[8], b[8];
            *(float4*)(a)     = *(const float4*)&As[kk][ty * 8];
            *(float4*)(a + 4) = *(const float4*)&As[kk][ty * 8 + 4];
            *(float4*)(b)     = *(const float4*)&Bs[kk][tx * 8];
            *(float4*)(b + 4) = *(const float4*)&Bs[kk][tx * 8 + 4];
            #pragma unroll
            for (int i = 0; i < 8; i++)
                #pragma unroll
                for (int j = 0; j < 8; j++)
                    acc[i][j] = fmaf(a[i], b[j], acc[i][j]);
        }
    }

    #pragma unroll
    for (int i = 0; i < 8; i++) {
        long long r = m0 + ty * 8 + i;
        #pragma unroll
        for (int jj = 0; jj < 8; jj += 4) {
            int c = n0 + tx * 8 + jj;
            float4 v;
            v.x = acc[i][jj]; v.y = acc[i][jj + 1];
            v.z = acc[i][jj + 2]; v.w = acc[i][jj + 3];
            if (bias) {
                v.x += bias[c]; v.y += bias[c + 1];
                v.z += bias[c + 2]; v.w += bias[c + 3];
            }
            if (act) {
                v.x = gelu_exact(v.x); v.y = gelu_exact(v.y);
                v.z = gelu_exact(v.z); v.w = gelu_exact(v.w);
            }
            *(float4*)(C + r * ldc + c) = v;
        }
    }
}

// ---------------- fused shift + scale + softmax (row-wise, in place on SC) ----
__global__ void __launch_bounds__(256) k_softmax(float* __restrict__ SC,
                                                 const float* __restrict__ P) {
    int row = blockIdx.x;                   // (b*H + h)*SEQ + m
    int m = row & (SEQ - 1);
    size_t base = (size_t)row * SEQ;
    int tid = threadIdx.x;
    __shared__ float sm[8];

    float v[4];
    float mx = -1e30f;
    #pragma unroll
    for (int q = 0; q < 4; q++) {
        int n = q * 256 + tid;
        float s = SC[base + n];
        if (n <= m) s += P[base + (n - m + SEQ - 1)];   // shift trick
        s *= 0.25f;                                     // HEADS^-0.5
        v[q] = s;
        mx = fmaxf(mx, s);
    }
    mx = block_max(mx, sm);
    float s = 0.f;
    #pragma unroll
    for (int q = 0; q < 4; q++) { v[q] = __expf(v[q] - mx); s += v[q]; }
    s = block_sum(s, sm);
    float inv = 1.f / s;
    #pragma unroll
    for (int q = 0; q < 4; q++) SC[base + q * 256 + tid] = v[q] * inv;
}

// ---------------- attn @ v : per (b,h)  C[S,64] = A[S,S] @ V[S,64] ----------
__global__ void __launch_bounds__(256) k_gemm_av(const float* __restrict__ SC,
                                                 const float* __restrict__ V,
                                                 float* __restrict__ C) {
    int z  = blockIdx.z;
    int bb = z >> 4, hh = z & 15;
    const float* A  = SC + (size_t)z * SEQ * SEQ;
    const float* Bv = V  + (size_t)bb * SEQ * DMODEL + hh * DHEAD;
    float*       Cp = C  + (size_t)bb * SEQ * DMODEL + hh * DHEAD;
    int m0 = blockIdx.y * 64;

    __shared__ float As[64][17];
    __shared__ float Bs[16][64];

    int tid = threadIdx.x;
    int tx = tid & 15, ty = tid >> 4;
    int arow = tid >> 2, acol = (tid & 3) << 2;
    int brow = tid >> 4, bcol = (tid & 15) << 2;

    float acc[4][4];
    #pragma unroll
    for (int i = 0; i < 4; i++)
        #pragma unroll
        for (int j = 0; j < 4; j++) acc[i][j] = 0.f;

    for (int k0 = 0; k0 < SEQ; k0 += 16) {
        float4 av = *(const float4*)(A  + (long long)(m0 + arow) * SEQ + k0 + acol);
        float4 bv = *(const float4*)(Bv + (long long)(k0 + brow) * DMODEL + bcol);
        __syncthreads();
        As[arow][acol + 0] = av.x; As[arow][acol + 1] = av.y;
        As[arow][acol + 2] = av.z; As[arow][acol + 3] = av.w;
        *(float4*)&Bs[brow][bcol] = bv;
        __syncthreads();
        #pragma unroll
        for (int kk = 0; kk < 16; kk++) {
            float4 b4 = *(const float4*)&Bs[kk][tx * 4];
            float a0 = As[ty * 4 + 0][kk], a1 = As[ty * 4 + 1][kk];
            float a2 = As[ty * 4 + 2][kk], a3 = As[ty * 4 + 3][kk];
            acc[0][0] = fmaf(a0, b4.x, acc[0][0]); acc[0][1] = fmaf(a0, b4.y, acc[0][1]);
            acc[0][2] = fmaf(a0, b4.z, acc[0][2]); acc[0][3] = fmaf(a0, b4.w, acc[0][3]);
            acc[1][0] = fmaf(a1, b4.x, acc[1][0]); acc[1][1] = fmaf(a1, b4.y, acc[1][1]);
            acc[1][2] = fmaf(a1, b4.z, acc[1][2]); acc[1][3] = fmaf(a1, b4.w, acc[1][3]);
            acc[2][0] = fmaf(a2, b4.x, acc[2][0]); acc[2][1] = fmaf(a2, b4.y, acc[2][1]);
            acc[2][2] = fmaf(a2, b4.z, acc[2][2]); acc[2][3] = fmaf(a2, b4.w, acc[2][3]);
            acc[3][0] = fmaf(a3, b4.x, acc[3][0]); acc[3][1] = fmaf(a3, b4.y, acc[3][1]);
            acc[3][2] = fmaf(a3, b4.z, acc[3][2]); acc[3][3] = fmaf(a3, b4.w, acc[3][3]);
        }
    }
    #pragma unroll
    for (int i = 0; i < 4; i++) {
        float4 v;
        v.x = acc[i][0]; v.y = acc[i][1]; v.z = acc[i][2]; v.w = acc[i][3];
        *(float4*)(Cp + (long long)(m0 + ty * 4 + i) * DMODEL + tx * 4) = v;
    }
}

// ---------------- residual add + LayerNorm ----------------
__global__ void __launch_bounds__(256) k_addln(const float* __restrict__ X,
                                               const float* __restrict__ R,
                                               const float* __restrict__ g,
                                               const float* __restrict__ b,
                                               float* __restrict__ dst) {
    int row = blockIdx.x;
    size_t base = (size_t)row * DMODEL;
    int tid = threadIdx.x;
    __shared__ float sm[8];

    float v[4];
    float s = 0.f;
    #pragma unroll
    for (int q = 0; q < 4; q++) {
        int c = q * 256 + tid;
        float x = X[base + c] + R[base + c];
        v[q] = x; s += x;
    }
    float mu = block_sum(s, sm) * (1.f / DMODEL);
    float s2 = 0.f;
    #pragma unroll
    for (int q = 0; q < 4; q++) { float d = v[q] - mu; s2 += d * d; }
    float var = block_sum(s2, sm) * (1.f / DMODEL);
    float rs = rsqrtf(var + 1e-5f);
    #pragma unroll
    for (int q = 0; q < 4; q++) {
        int c = q * 256 + tid;
        dst[base + c] = (v[q] - mu) * rs * g[c] + b[c];
    }
}

// ---------------- orchestration ----------------
extern "C" void kernel_launch(void* const* d_in, const int* in_sizes, int n_in,
                              void* d_out, int out_size) {
    (void)in_sizes; (void)n_in; (void)out_size;
    const int*   seq    = (const int*)  d_in[0];
    // d_in[1] mask (all true), d_in[2] cmems, d_in[3] mems: unused by reference
    const float* embed  = (const float*)d_in[4];
    const float* Wq     = (const float*)d_in[5];
    const float* Wk     = (const float*)d_in[6];
    const float* Wv     = (const float*)d_in[7];
    const float* Wo     = (const float*)d_in[8];
    const float* r_emb  = (const float*)d_in[9];
    const float* rwb    = (const float*)d_in[10];
    const float* r_bias = (const float*)d_in[11];
    const float* ln1g   = (const float*)d_in[12];
    const float* ln1b   = (const float*)d_in[13];
    const float* ln2g   = (const float*)d_in[14];
    const float* ln2b   = (const float*)d_in[15];
    const float* w1     = (const float*)d_in[16];
    const float* b1     = (const float*)d_in[17];
    const float* w2     = (const float*)d_in[18];
    const float* b2     = (const float*)d_in[19];

    float *X, *Q, *Kb, *V, *RQ, *T, *SC, *P, *Hf;
    cudaGetSymbolAddress((void**)&X,  g_X);
    cudaGetSymbolAddress((void**)&Q,  g_Q);
    cudaGetSymbolAddress((void**)&Kb, g_K);
    cudaGetSymbolAddress((void**)&V,  g_V);
    cudaGetSymbolAddress((void**)&RQ, g_RQ);
    cudaGetSymbolAddress((void**)&T,  g_T);
    cudaGetSymbolAddress((void**)&SC, g_SC);
    cudaGetSymbolAddress((void**)&P,  g_P);
    cudaGetSymbolAddress((void**)&Hf, g_H);

    const int M = BATCHN * SEQ;                       // 4096
    const long long sQb = (long long)SEQ * DMODEL;    // per-batch stride into Q/K/V
    const long long sSCb = (long long)NHEAD * SEQ * SEQ;
    const long long sSCh = (long long)SEQ * SEQ;

    k_embed<<<M, 256>>>(seq, embed, X);

    for (int l = 0; l < NLAYER; l++) {
        const float* wq = Wq + (size_t)l * DMODEL * DMODEL;
        const float* wk = Wk + (size_t)l * DMODEL * DMODEL;
        const float* wv = Wv + (size_t)l * DMODEL * DMODEL;
        const float* wo = Wo + (size_t)l * DMODEL * DMODEL;

        dim3 gproj(DMODEL / 128, M / 128, 1);         // (8,32)
        k_gemm_tn<<<gproj, 256>>>(M, DMODEL, DMODEL, X, DMODEL, 0, 0,
                                  wq, DMODEL, 0, 0, Q, DMODEL, 0, 0,
                                  nullptr, 0, 1, 0);
        k_gemm_tn<<<gproj, 256>>>(M, DMODEL, DMODEL, X, DMODEL, 0, 0,
                                  wk, DMODEL, 0, 0, Kb, DMODEL, 0, 0,
                                  nullptr, 0, 1, 0);
        k_gemm_tn<<<gproj, 256>>>(M, DMODEL, DMODEL, X, DMODEL, 0, 0,
                                  wv, DMODEL, 0, 0, V, DMODEL, 0, 0,
                                  nullptr, 0, 1, 0);

        k_addrwb<<<(M * DMODEL) / 256, 256>>>(Q, rwb + (size_t)l * NHEAD * DHEAD, RQ);

        // AC = (q + rwb) @ k^T, batched over (b,h)
        dim3 gsc(SEQ / 128, SEQ / 128, BATCHN * NHEAD);
        k_gemm_tn<<<gsc, 256>>>(SEQ, SEQ, DHEAD,
                                RQ, DMODEL, sQb, DHEAD,
                                Kb, DMODEL, sQb, DHEAD,
                                SC, SEQ, sSCb, sSCh,
                                nullptr, 0, NHEAD, 0);
        // P = q @ re^T + rb, batched over (b,h); re shared across batch
        k_gemm_tn<<<gsc, 256>>>(SEQ, SEQ, DHEAD,
                                Q, DMODEL, sQb, DHEAD,
                                r_emb + ((size_t)l * NHEAD * MAXKLEN + ROFF) * DHEAD,
                                DHEAD, 0, (long long)MAXKLEN * DHEAD,
                                P, SEQ, sSCb, sSCh,
                                r_bias + (size_t)l * NHEAD * MAXKLEN + ROFF,
                                MAXKLEN, NHEAD, 0);

        k_softmax<<<BATCHN * NHEAD * SEQ, 256>>>(SC, P);

        dim3 gav(1, SEQ / 64, BATCHN * NHEAD);
        k_gemm_av<<<gav, 256>>>(SC, V, T);

        // output projection -> Q (free), then residual + LN1 -> X
        k_gemm_tn<<<gproj, 256>>>(M, DMODEL, DMODEL, T, DMODEL, 0, 0,
                                  wo, DMODEL, 0, 0, Q, DMODEL, 0, 0,
                                  nullptr, 0, 1, 0);
        k_addln<<<M, 256>>>(X, Q, ln1g + (size_t)l * DMODEL, ln1b + (size_t)l * DMODEL, X);

        // FFN
        dim3 gff1(FFDIM / 128, M / 128, 1);
        k_gemm_tn<<<gff1, 256>>>(M, FFDIM, DMODEL, X, DMODEL, 0, 0,
                                 w1 + (size_t)l * FFDIM * DMODEL, DMODEL, 0, 0,
                                 Hf, FFDIM, 0, 0,
                                 b1 + (size_t)l * FFDIM, 0, 1, 1 /*gelu*/);
        dim3 gff2(DMODEL / 128, M / 128, 1);
        k_gemm_tn<<<gff2, 256>>>(M, DMODEL, FFDIM, Hf, FFDIM, 0, 0,
                                 w2 + (size_t)l * DMODEL * FFDIM, FFDIM, 0, 0,
                                 Q, DMODEL, 0, 0,
                                 b2 + (size_t)l * DMODEL, 0, 1, 0);

        float* dst = (l == NLAYER - 1) ? (float*)d_out : X;
        k_addln<<<M, 256>>>(X, Q, ln2g + (size_t)l * DMODEL, ln2b + (size_t)l * DMODEL, dst);
    }
}

// round 7
// speedup vs baseline: 3.0827x; 3.0827x over previous
#include <cuda_runtime.h>
#include <math.h>
#include <stdint.h>

#define BATCHN 4
#define SEQ    1024
#define DMODEL 1024
#define NHEAD  16
#define DHEAD  64
#define FFDIM  4096
#define NLAYER 4
#define MAXKLEN 1664
#define ROFF   640          // MAXKLEN - SEQ

// ---------------- scratch (device globals: allocation-free) ----------------
__device__ float g_X [BATCHN*SEQ*DMODEL];
__device__ float g_Q [BATCHN*SEQ*DMODEL];
__device__ float g_K [BATCHN*SEQ*DMODEL];
__device__ float g_V [BATCHN*SEQ*DMODEL];
__device__ float g_RQ[BATCHN*SEQ*DMODEL];
__device__ float g_T [BATCHN*SEQ*DMODEL];
__device__ float g_SC[(size_t)BATCHN*NHEAD*SEQ*SEQ];   // scores -> attn (in place)
__device__ float g_P [(size_t)BATCHN*NHEAD*SEQ*SEQ];   // q @ re^T + rb
__device__ float g_H [BATCHN*SEQ*FFDIM];               // FF hidden

// ---------------- helpers ----------------
__device__ __forceinline__ float gelu_exact(float x) {
    return 0.5f * x * (1.0f + erff(x * 0.70710678118654752f));
}

__device__ __forceinline__ uint32_t f2tf32(float x) {
    uint32_t u;
    asm("cvt.rna.tf32.f32 %0, %1;" : "=r"(u) : "f"(x));
    return u;
}

__device__ __forceinline__ void mma_tf32(float c[4],
                                         uint32_t a0, uint32_t a1, uint32_t a2, uint32_t a3,
                                         uint32_t b0, uint32_t b1) {
    asm volatile(
        "mma.sync.aligned.m16n8k8.row.col.f32.tf32.tf32.f32 "
        "{%0,%1,%2,%3}, {%4,%5,%6,%7}, {%8,%9}, {%0,%1,%2,%3};"
        : "+f"(c[0]), "+f"(c[1]), "+f"(c[2]), "+f"(c[3])
        : "r"(a0), "r"(a1), "r"(a2), "r"(a3), "r"(b0), "r"(b1));
}

__device__ __forceinline__ uint32_t sptr(const void* p) {
    return (uint32_t)__cvta_generic_to_shared(p);
}
__device__ __forceinline__ void cpasync16(uint32_t s, const void* g) {
    asm volatile("cp.async.cg.shared.global [%0], [%1], 16;\n" :: "r"(s), "l"(g));
}
__device__ __forceinline__ void cpcommit() { asm volatile("cp.async.commit_group;\n"); }

__device__ __forceinline__ float block_sum(float x, float* sm) {
    #pragma unroll
    for (int o = 16; o > 0; o >>= 1) x += __shfl_xor_sync(0xffffffffu, x, o);
    if ((threadIdx.x & 31) == 0) sm[threadIdx.x >> 5] = x;
    __syncthreads();
    float t = 0.f;
    #pragma unroll
    for (int w = 0; w < 8; w++) t += sm[w];
    __syncthreads();
    return t;
}

__device__ __forceinline__ float block_max(float x, float* sm) {
    #pragma unroll
    for (int o = 16; o > 0; o >>= 1) x = fmaxf(x, __shfl_xor_sync(0xffffffffu, x, o));
    if ((threadIdx.x & 31) == 0) sm[threadIdx.x >> 5] = x;
    __syncthreads();
    float t = sm[0];
    #pragma unroll
    for (int w = 1; w < 8; w++) t = fmaxf(t, sm[w]);
    __syncthreads();
    return t;
}

// ---------------- embed gather ----------------
__global__ void __launch_bounds__(256) k_embed(const int* __restrict__ seq,
                                               const float* __restrict__ emb,
                                               float* __restrict__ X) {
    int row = blockIdx.x;
    int tok = seq[row];
    const float4* src = (const float4*)(emb + (size_t)tok * DMODEL);
    float4* dst = (float4*)(X + (size_t)row * DMODEL);
    dst[threadIdx.x] = src[threadIdx.x];
}

// ---------------- q + r_w_bias ----------------
__global__ void __launch_bounds__(256) k_addrwb(const float* __restrict__ Q,
                                                const float* __restrict__ rwb,
                                                float* __restrict__ RQ) {
    size_t i = (size_t)blockIdx.x * blockDim.x + threadIdx.x;
    RQ[i] = Q[i] + rwb[i & (DMODEL - 1)];
}

// ---------------- TF32 tensor-core GEMM ----------------
// C[M,N] = A[M,K] @ op(B),  op = B[N,K]^T (TRANSB) or B[K,N] (!TRANSB)
// Block tile 128 x BN x 16, 256 threads = 2x4 warps, warp tile 64 x (BN/4).
// Double-buffered cp.async. Batched over z=(b,h). Optional bias/GELU epilogue.
// skew!=0: skip blocks never read by the shift-softmax (bx+by <= 6).
template<int BN, bool TRANSB>
__global__ void __launch_bounds__(256) k_mma(
    int M, int N, int K,
    const float* __restrict__ A, int lda, long long sAb, long long sAh,
    const float* __restrict__ B, int ldb, long long sBb, long long sBh,
    float* __restrict__ C, int ldc, long long sCb, long long sCh,
    const float* __restrict__ bias, long long sbias_h,
    int Hdiv, int act, int skew)
{
    if (skew && (int)(blockIdx.x + blockIdx.y) <= 6) return;

    constexpr int BM = 128, BK = 16;
    constexpr int AST = BK + 4;                    // 20: stride ≡ 4 mod 32
    constexpr int BROWS = TRANSB ? BN : BK;
    constexpr int BST = TRANSB ? (BK + 4) : (BN + 8);
    constexpr int WN = BN / 4;                     // 32 or 16 cols per warp
    constexpr int NT = WN / 8;                     // 4 or 2 n-tiles

    __shared__ float As[2][BM][AST];
    __shared__ float Bs[2][BROWS][BST];

    int z = blockIdx.z;
    int bb = z / Hdiv, hh = z % Hdiv;
    A += (long long)bb * sAb + (long long)hh * sAh;
    B += (long long)bb * sBb + (long long)hh * sBh;
    C += (long long)bb * sCb + (long long)hh * sCh;
    if (bias) bias += (long long)hh * sbias_h;

    const int tid  = threadIdx.x;
    const int lane = tid & 31, wid = tid >> 5;
    const int gid  = lane >> 2, tig = lane & 3;
    const int wm   = wid & 1,   wn  = wid >> 1;
    const int m0 = blockIdx.y * BM, n0 = blockIdx.x * BN;

    float acc[4][NT][4];
    #pragma unroll
    for (int i = 0; i < 4; i++)
        #pragma unroll
        for (int j = 0; j < NT; j++)
            #pragma unroll
            for (int q = 0; q < 4; q++) acc[i][j][q] = 0.f;

    const int iters = K / BK;

    auto stage = [&](int it, int buf) {
        int k0 = it * BK;
        // A tile: BM x BK
        #pragma unroll
        for (int i = 0; i < (BM * BK / 4) / 256; i++) {
            int idx = tid + i * 256;
            int r = idx >> 2, c4 = idx & 3;
            cpasync16(sptr(&As[buf][r][c4 * 4]),
                      A + (long long)(m0 + r) * lda + k0 + c4 * 4);
        }
        if (TRANSB) {
            // B tile: BN x BK (natural [n][k])
            #pragma unroll
            for (int i = 0; i < (BN * BK / 4) / 256; i++) {
                int idx = tid + i * 256;
                int r = idx >> 2, c4 = idx & 3;
                cpasync16(sptr(&Bs[buf][r][c4 * 4]),
                          B + (long long)(n0 + r) * ldb + k0 + c4 * 4);
            }
        } else {
            // B tile: BK x BN (natural [k][n])
            constexpr int C4 = BN / 4;
            #pragma unroll
            for (int i = 0; i < (BK * BN / 4) / 256; i++) {
                int idx = tid + i * 256;
                int r = idx / C4, c4 = idx % C4;
                cpasync16(sptr(&Bs[buf][r][c4 * 4]),
                          B + (long long)(k0 + r) * ldb + n0 + c4 * 4);
            }
        }
        cpcommit();
    };

    auto compute = [&](int buf) {
        #pragma unroll
        for (int ks = 0; ks < 2; ks++) {
            int kk = ks * 8;
            uint32_t af[4][4], bf[NT][2];
            #pragma unroll
            for (int mt = 0; mt < 4; mt++) {
                int rm = wm * 64 + mt * 16;
                af[mt][0] = f2tf32(As[buf][rm + gid    ][kk + tig    ]);
                af[mt][1] = f2tf32(As[buf][rm + gid + 8][kk + tig    ]);
                af[mt][2] = f2tf32(As[buf][rm + gid    ][kk + tig + 4]);
                af[mt][3] = f2tf32(As[buf][rm + gid + 8][kk + tig + 4]);
            }
            #pragma unroll
            for (int nt = 0; nt < NT; nt++) {
                int cb = wn * WN + nt * 8 + gid;
                if (TRANSB) {
                    bf[nt][0] = f2tf32(Bs[buf][cb][kk + tig    ]);
                    bf[nt][1] = f2tf32(Bs[buf][cb][kk + tig + 4]);
                } else {
                    bf[nt][0] = f2tf32(Bs[buf][kk + tig    ][cb]);
                    bf[nt][1] = f2tf32(Bs[buf][kk + tig + 4][cb]);
                }
            }
            #pragma unroll
            for (int mt = 0; mt < 4; mt++)
                #pragma unroll
                for (int nt = 0; nt < NT; nt++)
                    mma_tf32(acc[mt][nt], af[mt][0], af[mt][1], af[mt][2], af[mt][3],
                             bf[nt][0], bf[nt][1]);
        }
    };

    stage(0, 0);
    for (int it = 0; it < iters; ++it) {
        int buf = it & 1;
        if (it + 1 < iters) {
            stage(it + 1, buf ^ 1);
            asm volatile("cp.async.wait_group 1;\n");
        } else {
            asm volatile("cp.async.wait_group 0;\n");
        }
        __syncthreads();
        compute(buf);
        __syncthreads();
    }

    // epilogue
    #pragma unroll
    for (int mt = 0; mt < 4; mt++) {
        int r0 = m0 + wm * 64 + mt * 16 + gid;
        #pragma unroll
        for (int nt = 0; nt < NT; nt++) {
            int c = n0 + wn * WN + nt * 8 + 2 * tig;
            float v0 = acc[mt][nt][0], v1 = acc[mt][nt][1];
            float v2 = acc[mt][nt][2], v3 = acc[mt][nt][3];
            if (bias) {
                float q0 = bias[c], q1 = bias[c + 1];
                v0 += q0; v1 += q1; v2 += q0; v3 += q1;
            }
            if (act) {
                v0 = gelu_exact(v0); v1 = gelu_exact(v1);
                v2 = gelu_exact(v2); v3 = gelu_exact(v3);
            }
            *(float2*)(C + (long long)r0 * ldc + c)       = make_float2(v0, v1);
            *(float2*)(C + (long long)(r0 + 8) * ldc + c) = make_float2(v2, v3);
        }
    }
}

// ---------------- fused shift + scale + softmax (row-wise, in place on SC) ----
__global__ void __launch_bounds__(256) k_softmax(float* __restrict__ SC,
                                                 const float* __restrict__ P) {
    int row = blockIdx.x;                   // (b*H + h)*SEQ + m
    int m = row & (SEQ - 1);
    size_t base = (size_t)row * SEQ;
    int tid = threadIdx.x;
    __shared__ float sm[8];

    float v[4];
    float mx = -1e30f;
    #pragma unroll
    for (int q = 0; q < 4; q++) {
        int n = q * 256 + tid;
        float s = SC[base + n];
        if (n <= m) s += P[base + (n - m + SEQ - 1)];   // shift trick
        s *= 0.25f;                                     // HEADS^-0.5
        v[q] = s;
        mx = fmaxf(mx, s);
    }
    mx = block_max(mx, sm);
    float s = 0.f;
    #pragma unroll
    for (int q = 0; q < 4; q++) { v[q] = __expf(v[q] - mx); s += v[q]; }
    s = block_sum(s, sm);
    float inv = 1.f / s;
    #pragma unroll
    for (int q = 0; q < 4; q++) SC[base + q * 256 + tid] = v[q] * inv;
}

// ---------------- residual add + LayerNorm ----------------
__global__ void __launch_bounds__(256) k_addln(const float* __restrict__ X,
                                               const float* __restrict__ R,
                                               const float* __restrict__ g,
                                               const float* __restrict__ b,
                                               float* __restrict__ dst) {
    int row = blockIdx.x;
    size_t base = (size_t)row * DMODEL;
    int tid = threadIdx.x;
    __shared__ float sm[8];

    float v[4];
    float s = 0.f;
    #pragma unroll
    for (int q = 0; q < 4; q++) {
        int c = q * 256 + tid;
        float x = X[base + c] + R[base + c];
        v[q] = x; s += x;
    }
    float mu = block_sum(s, sm) * (1.f / DMODEL);
    float s2 = 0.f;
    #pragma unroll
    for (int q = 0; q < 4; q++) { float d = v[q] - mu; s2 += d * d; }
    float var = block_sum(s2, sm) * (1.f / DMODEL);
    float rs = rsqrtf(var + 1e-5f);
    #pragma unroll
    for (int q = 0; q < 4; q++) {
        int c = q * 256 + tid;
        dst[base + c] = (v[q] - mu) * rs * g[c] + b[c];
    }
}

// ---------------- orchestration ----------------
extern "C" void kernel_launch(void* const* d_in, const int* in_sizes, int n_in,
                              void* d_out, int out_size) {
    (void)in_sizes; (void)n_in; (void)out_size;
    const int*   seq    = (const int*)  d_in[0];
    // d_in[1] mask (all true), d_in[2] cmems, d_in[3] mems: unused by reference
    const float* embed  = (const float*)d_in[4];
    const float* Wq     = (const float*)d_in[5];
    const float* Wk     = (const float*)d_in[6];
    const float* Wv     = (const float*)d_in[7];
    const float* Wo     = (const float*)d_in[8];
    const float* r_emb  = (const float*)d_in[9];
    const float* rwb    = (const float*)d_in[10];
    const float* r_bias = (const float*)d_in[11];
    const float* ln1g   = (const float*)d_in[12];
    const float* ln1b   = (const float*)d_in[13];
    const float* ln2g   = (const float*)d_in[14];
    const float* ln2b   = (const float*)d_in[15];
    const float* w1     = (const float*)d_in[16];
    const float* b1     = (const float*)d_in[17];
    const float* w2     = (const float*)d_in[18];
    const float* b2     = (const float*)d_in[19];

    float *X, *Q, *Kb, *V, *RQ, *T, *SC, *P, *Hf;
    cudaGetSymbolAddress((void**)&X,  g_X);
    cudaGetSymbolAddress((void**)&Q,  g_Q);
    cudaGetSymbolAddress((void**)&Kb, g_K);
    cudaGetSymbolAddress((void**)&V,  g_V);
    cudaGetSymbolAddress((void**)&RQ, g_RQ);
    cudaGetSymbolAddress((void**)&T,  g_T);
    cudaGetSymbolAddress((void**)&SC, g_SC);
    cudaGetSymbolAddress((void**)&P,  g_P);
    cudaGetSymbolAddress((void**)&Hf, g_H);

    const int M = BATCHN * SEQ;                       // 4096
    const long long sQb  = (long long)SEQ * DMODEL;
    const long long sSCb = (long long)NHEAD * SEQ * SEQ;
    const long long sSCh = (long long)SEQ * SEQ;

    k_embed<<<M, 256>>>(seq, embed, X);

    for (int l = 0; l < NLAYER; l++) {
        const float* wq = Wq + (size_t)l * DMODEL * DMODEL;
        const float* wk = Wk + (size_t)l * DMODEL * DMODEL;
        const float* wv = Wv + (size_t)l * DMODEL * DMODEL;
        const float* wo = Wo + (size_t)l * DMODEL * DMODEL;

        dim3 gproj(DMODEL / 128, M / 128, 1);         // (8,32)
        k_mma<128, true><<<gproj, 256>>>(M, DMODEL, DMODEL, X, DMODEL, 0, 0,
                                         wq, DMODEL, 0, 0, Q, DMODEL, 0, 0,
                                         nullptr, 0, 1, 0, 0);
        k_mma<128, true><<<gproj, 256>>>(M, DMODEL, DMODEL, X, DMODEL, 0, 0,
                                         wk, DMODEL, 0, 0, Kb, DMODEL, 0, 0,
                                         nullptr, 0, 1, 0, 0);
        k_mma<128, true><<<gproj, 256>>>(M, DMODEL, DMODEL, X, DMODEL, 0, 0,
                                         wv, DMODEL, 0, 0, V, DMODEL, 0, 0,
                                         nullptr, 0, 1, 0, 0);

        k_addrwb<<<(M * DMODEL) / 256, 256>>>(Q, rwb + (size_t)l * NHEAD * DHEAD, RQ);

        // AC = (q + rwb) @ k^T, batched over (b,h)
        dim3 gsc(SEQ / 128, SEQ / 128, BATCHN * NHEAD);
        k_mma<128, true><<<gsc, 256>>>(SEQ, SEQ, DHEAD,
                                       RQ, DMODEL, sQb, DHEAD,
                                       Kb, DMODEL, sQb, DHEAD,
                                       SC, SEQ, sSCb, sSCh,
                                       nullptr, 0, NHEAD, 0, 0);
        // P = q @ re^T + rb, batched over (b,h); re shared across batch.
        // skew=1: skip blocks never read by the shift (bx+by <= 6).
        k_mma<128, true><<<gsc, 256>>>(SEQ, SEQ, DHEAD,
                                       Q, DMODEL, sQb, DHEAD,
                                       r_emb + ((size_t)l * NHEAD * MAXKLEN + ROFF) * DHEAD,
                                       DHEAD, 0, (long long)MAXKLEN * DHEAD,
                                       P, SEQ, sSCb, sSCh,
                                       r_bias + (size_t)l * NHEAD * MAXKLEN + ROFF,
                                       MAXKLEN, NHEAD, 0, 1);

        k_softmax<<<BATCHN * NHEAD * SEQ, 256>>>(SC, P);

        // attn @ v  (NN gemm, N=64 per head)
        dim3 gav(1, SEQ / 128, BATCHN * NHEAD);
        k_mma<64, false><<<gav, 256>>>(SEQ, DHEAD, SEQ,
                                       SC, SEQ, sSCb, sSCh,
                                       V, DMODEL, sQb, DHEAD,
                                       T, DMODEL, sQb, DHEAD,
                                       nullptr, 0, NHEAD, 0, 0);

        // output projection -> Q (free), then residual + LN1 -> X
        k_mma<128, true><<<gproj, 256>>>(M, DMODEL, DMODEL, T, DMODEL, 0, 0,
                                         wo, DMODEL, 0, 0, Q, DMODEL, 0, 0,
                                         nullptr, 0, 1, 0, 0);
        k_addln<<<M, 256>>>(X, Q, ln1g + (size_t)l * DMODEL, ln1b + (size_t)l * DMODEL, X);

        // FFN
        dim3 gff1(FFDIM / 128, M / 128, 1);
        k_mma<128, true><<<gff1, 256>>>(M, FFDIM, DMODEL, X, DMODEL, 0, 0,
                                        w1 + (size_t)l * FFDIM * DMODEL, DMODEL, 0, 0,
                                        Hf, FFDIM, 0, 0,
                                        b1 + (size_t)l * FFDIM, 0, 1, 1 /*gelu*/, 0);
        dim3 gff2(DMODEL / 128, M / 128, 1);
        k_mma<128, true><<<gff2, 256>>>(M, DMODEL, FFDIM, Hf, FFDIM, 0, 0,
                                        w2 + (size_t)l * DMODEL * FFDIM, FFDIM, 0, 0,
                                        Q, DMODEL, 0, 0,
                                        b2 + (size_t)l * DMODEL, 0, 1, 0, 0);

        float* dst = (l == NLAYER - 1) ? (float*)d_out : X;
        k_addln<<<M, 256>>>(X, Q, ln2g + (size_t)l * DMODEL, ln2b + (size_t)l * DMODEL, dst);
    }
}